// round 16
// baseline (speedup 1.0000x reference)
// R15 re-bench: previous run failed with cudaErrorSystemNotReady at harness
// init (fabric manager not up) — infra transient, kernel never executed.
#include <cuda_runtime.h>
#include <cuda_bf16.h>
#include <cstdint>
#include <cstddef>

#define DM   512
#define NH   8
#define HD   64
#define PS   4
#define BB   4
#define TT   4096
#define PP   1024

// ---------------------------------------------------------------------------
// scratch (device globals; no allocation allowed)
// ---------------------------------------------------------------------------
__device__ __align__(16) __nv_bfloat16 g_Qh[(size_t)BB * TT * DM];
__device__ __align__(16) __nv_bfloat16 g_Ql[(size_t)BB * TT * DM];
__device__ __align__(16) __nv_bfloat16 g_Kh[(size_t)BB * PP * DM];
__device__ __align__(16) __nv_bfloat16 g_Kl[(size_t)BB * PP * DM];
__device__ __align__(16) __nv_bfloat16 g_Vh[(size_t)BB * PP * DM];
__device__ __align__(16) __nv_bfloat16 g_Vl[(size_t)BB * PP * DM];

__device__ __align__(16) __nv_bfloat16 g_tok_hi[(size_t)BB * TT * DM];
__device__ __align__(16) __nv_bfloat16 g_tok_lo[(size_t)BB * TT * DM];
__device__ __align__(16) __nv_bfloat16 g_pat_hi[(size_t)BB * PP * DM];
__device__ __align__(16) __nv_bfloat16 g_pat_lo[(size_t)BB * PP * DM];
__device__ __align__(16) __nv_bfloat16 g_ctx_hi[(size_t)BB * TT * DM];
__device__ __align__(16) __nv_bfloat16 g_ctx_lo[(size_t)BB * TT * DM];
__device__ __align__(16) __nv_bfloat16 g_Wt_hi[4 * DM * DM];
__device__ __align__(16) __nv_bfloat16 g_Wt_lo[4 * DM * DM];

// ---------------------------------------------------------------------------
// base-ISA helpers (plain sm_103 target)
// ---------------------------------------------------------------------------
__device__ __forceinline__ uint32_t smem_u32(const void* p) {
    uint32_t a;
    asm("{ .reg .u64 t; cvta.to.shared.u64 t, %1; cvt.u32.u64 %0, t; }"
        : "=r"(a) : "l"(p));
    return a;
}

__device__ __forceinline__ void cp16(uint32_t saddr, const void* gaddr) {
    asm volatile("cp.async.cg.shared.global [%0], [%1], 16;"
                 :: "r"(saddr), "l"(gaddr));
}
__device__ __forceinline__ void cp_commit() {
    asm volatile("cp.async.commit_group;");
}
template <int N>
__device__ __forceinline__ void cp_wait() {
    asm volatile("cp.async.wait_group %0;" :: "n"(N));
}

__device__ __forceinline__ void ldsm_x4(uint32_t& r0, uint32_t& r1,
                                        uint32_t& r2, uint32_t& r3, uint32_t addr) {
    asm volatile("ldmatrix.sync.aligned.m8n8.x4.shared.b16 {%0,%1,%2,%3}, [%4];"
                 : "=r"(r0), "=r"(r1), "=r"(r2), "=r"(r3) : "r"(addr));
}
__device__ __forceinline__ void ldsm_x4_t(uint32_t& r0, uint32_t& r1,
                                          uint32_t& r2, uint32_t& r3, uint32_t addr) {
    asm volatile("ldmatrix.sync.aligned.m8n8.x4.trans.shared.b16 {%0,%1,%2,%3}, [%4];"
                 : "=r"(r0), "=r"(r1), "=r"(r2), "=r"(r3) : "r"(addr));
}

__device__ __forceinline__ void mma16816(float* d, const uint32_t* a, const uint32_t* b) {
    asm volatile(
        "mma.sync.aligned.m16n8k16.row.col.f32.bf16.bf16.f32 "
        "{%0,%1,%2,%3}, {%4,%5,%6,%7}, {%8,%9}, {%0,%1,%2,%3};"
        : "+f"(d[0]), "+f"(d[1]), "+f"(d[2]), "+f"(d[3])
        : "r"(a[0]), "r"(a[1]), "r"(a[2]), "r"(a[3]), "r"(b[0]), "r"(b[1]));
}

__device__ __forceinline__ void split2(float v0, float v1, uint32_t& hi, uint32_t& lo) {
    __nv_bfloat16 h0 = __float2bfloat16_rn(v0);
    __nv_bfloat16 h1 = __float2bfloat16_rn(v1);
    __nv_bfloat162 hv = __halves2bfloat162(h0, h1);
    __nv_bfloat162 lv = __halves2bfloat162(
        __float2bfloat16_rn(v0 - __bfloat162float(h0)),
        __float2bfloat16_rn(v1 - __bfloat162float(h1)));
    hi = *(uint32_t*)&hv;
    lo = *(uint32_t*)&lv;
}

// ---------------------------------------------------------------------------
// fp32 -> (bf16 hi, bf16 lo) split, vectorized
// ---------------------------------------------------------------------------
__global__ void conv_hilo(const float4* __restrict__ x,
                          __nv_bfloat162* __restrict__ hi,
                          __nv_bfloat162* __restrict__ lo, int n4)
{
    int i = blockIdx.x * blockDim.x + threadIdx.x;
    if (i >= n4) return;
    float4 v = x[i];
    uint32_t h0, l0, h1, l1;
    split2(v.x, v.y, h0, l0);
    split2(v.z, v.w, h1, l1);
    hi[2 * i + 0] = *(__nv_bfloat162*)&h0;
    hi[2 * i + 1] = *(__nv_bfloat162*)&h1;
    lo[2 * i + 0] = *(__nv_bfloat162*)&l0;
    lo[2 * i + 1] = *(__nv_bfloat162*)&l1;
}

// ---------------------------------------------------------------------------
// all 4 weights -> transposed hi/lo bf16, one launch (z picks the matrix)
// ---------------------------------------------------------------------------
__global__ void conv_wt4(const float* __restrict__ Wq, const float* __restrict__ Wk,
                         const float* __restrict__ Wv, const float* __restrict__ Wo,
                         __nv_bfloat16* __restrict__ whtBase,
                         __nv_bfloat16* __restrict__ wltBase)
{
    __shared__ float t[32][33];
    const int z = blockIdx.z;
    const float* W = (z == 0) ? Wq : (z == 1) ? Wk : (z == 2) ? Wv : Wo;
    __nv_bfloat16* wht = whtBase + (size_t)z * DM * DM;
    __nv_bfloat16* wlt = wltBase + (size_t)z * DM * DM;

    const int k0 = blockIdx.y * 32, n0 = blockIdx.x * 32;
    const int tx = threadIdx.x, ty = threadIdx.y;
    #pragma unroll
    for (int j = ty; j < 32; j += 8)
        t[j][tx] = W[(size_t)(k0 + j) * DM + n0 + tx];
    __syncthreads();
    #pragma unroll
    for (int j = ty; j < 32; j += 8) {
        float v = t[tx][j];
        __nv_bfloat16 h = __float2bfloat16_rn(v);
        wht[(size_t)(n0 + j) * DM + k0 + tx] = h;
        wlt[(size_t)(n0 + j) * DM + k0 + tx] =
            __float2bfloat16_rn(v - __bfloat162float(h));
    }
}

// ---------------------------------------------------------------------------
// double-buffered HMMA GEMM mainloop (128x128 CTA tile, 8 warps 2x4, K chunk 64)
// ---------------------------------------------------------------------------
#define GP     144
#define OFF_AH 0
#define OFF_AL (128 * GP)
#define OFF_BH (2 * 128 * GP)
#define OFF_BL (3 * 128 * GP)
#define GSTAGE (4 * 128 * GP)              // 73728 B / stage
#define GSMEM  (2 * GSTAGE)                // 147456 B

__device__ __forceinline__ void gemm_fill(
    uint32_t stg, int tid,
    const char* gAh, const char* gAl, const char* gBh, const char* gBl,
    size_t koff)
{
    #pragma unroll
    for (int i = 0; i < 4; i++) {
        int idx = tid + (i << 8);
        int r = idx >> 3, cb = (idx & 7) << 4;
        size_t go = (size_t)r * (DM * 2) + koff + cb;
        uint32_t so = r * GP + cb;
        cp16(stg + OFF_AH + so, gAh + go);
        cp16(stg + OFF_AL + so, gAl + go);
        cp16(stg + OFF_BH + so, gBh + go);
        cp16(stg + OFF_BL + so, gBl + go);
    }
}

__device__ __forceinline__ void gemm_mainloop(
    uint32_t sb, int tid, int wm, int wn, int lid,
    const char* gAh, const char* gAl, const char* gBh, const char* gBl,
    float acc[4][4][4])
{
    const int a_row = (wm << 6) + (lid & 15);
    const int a_cb  = (lid >> 4) << 4;
    const int b_sub = lid >> 3;
    const int b_row = (wn << 5) + ((b_sub & 1) << 3) + (lid & 7);
    const int b_cb  = (b_sub >> 1) << 4;

    gemm_fill(sb, tid, gAh, gAl, gBh, gBl, 0);
    cp_commit();

    for (int ck = 0; ck < 8; ck++) {
        const uint32_t stg = sb + (uint32_t)(ck & 1) * GSTAGE;
        if (ck < 7) {
            gemm_fill(sb + (uint32_t)((ck + 1) & 1) * GSTAGE, tid,
                      gAh, gAl, gBh, gBl, (size_t)(ck + 1) << 7);
            cp_commit();
            cp_wait<1>();
        } else {
            cp_wait<0>();
        }
        __syncthreads();

        #pragma unroll
        for (int ks = 0; ks < 4; ks++) {
            const int kb = ks << 5;

            uint32_t ah[4][4], al[4][4];
            #pragma unroll
            for (int mt = 0; mt < 4; mt++) {
                uint32_t ad = stg + (a_row + (mt << 4)) * GP + kb + a_cb;
                ldsm_x4(ah[mt][0], ah[mt][1], ah[mt][2], ah[mt][3], OFF_AH + ad);
                ldsm_x4(al[mt][0], al[mt][1], al[mt][2], al[mt][3], OFF_AL + ad);
            }
            uint32_t bh[4][2], bl[4][2];
            #pragma unroll
            for (int pr = 0; pr < 2; pr++) {
                uint32_t bd = stg + (b_row + (pr << 4)) * GP + kb + b_cb;
                uint32_t r0, r1, r2, r3;
                ldsm_x4(r0, r1, r2, r3, OFF_BH + bd);
                bh[2 * pr][0] = r0; bh[2 * pr + 1][0] = r1;
                bh[2 * pr][1] = r2; bh[2 * pr + 1][1] = r3;
                ldsm_x4(r0, r1, r2, r3, OFF_BL + bd);
                bl[2 * pr][0] = r0; bl[2 * pr + 1][0] = r1;
                bl[2 * pr][1] = r2; bl[2 * pr + 1][1] = r3;
            }

            #pragma unroll
            for (int mt = 0; mt < 4; mt++)
                #pragma unroll
                for (int nt = 0; nt < 4; nt++) {
                    mma16816(acc[mt][nt], ah[mt], bh[nt]);
                    mma16816(acc[mt][nt], ah[mt], bl[nt]);
                    mma16816(acc[mt][nt], al[mt], bh[nt]);
                }
        }
        __syncthreads();
    }
}

// ---------------------------------------------------------------------------
// fused QKV GEMM: grid (4, 192). y<128: Q rows; y in [128,160): K; else V.
// Q output pre-scaled by 1/sqrt(HD) = 0.125. bf16 hi/lo epilogue.
// ---------------------------------------------------------------------------
__global__ __launch_bounds__(256) void qkv_gemm(
    const __nv_bfloat16* __restrict__ tkh, const __nv_bfloat16* __restrict__ tkl,
    const __nv_bfloat16* __restrict__ pth, const __nv_bfloat16* __restrict__ ptl,
    const __nv_bfloat16* __restrict__ wth, const __nv_bfloat16* __restrict__ wtl,
    const float* __restrict__ bq, const float* __restrict__ bk,
    const float* __restrict__ bv,
    __nv_bfloat16* __restrict__ qh, __nv_bfloat16* __restrict__ ql,
    __nv_bfloat16* __restrict__ kh, __nv_bfloat16* __restrict__ kl,
    __nv_bfloat16* __restrict__ vh, __nv_bfloat16* __restrict__ vl)
{
    extern __shared__ char smg[];
    const uint32_t sb = smem_u32(smg);
    const int tid = threadIdx.x, wid = tid >> 5, lid = tid & 31;
    const int wm = wid >> 2, wn = wid & 3;

    const int by = blockIdx.y;
    const __nv_bfloat16 *Ahi, *Alo;
    const float* bias;
    __nv_bfloat16 *Chi, *Clo;
    int widx, mblk;
    float sc;
    if (by < 128)      { Ahi = tkh; Alo = tkl; bias = bq; Chi = qh; Clo = ql; widx = 0; mblk = by;       sc = 0.125f; }
    else if (by < 160) { Ahi = pth; Alo = ptl; bias = bk; Chi = kh; Clo = kl; widx = 1; mblk = by - 128; sc = 1.0f; }
    else               { Ahi = pth; Alo = ptl; bias = bv; Chi = vh; Clo = vl; widx = 2; mblk = by - 160; sc = 1.0f; }

    const int m0 = mblk << 7, n0 = blockIdx.x << 7;
    const __nv_bfloat16* Bhi = wth + (size_t)widx * DM * DM;
    const __nv_bfloat16* Blo = wtl + (size_t)widx * DM * DM;

    float acc[4][4][4];
    #pragma unroll
    for (int i = 0; i < 4; i++)
        #pragma unroll
        for (int j = 0; j < 4; j++)
            #pragma unroll
            for (int c = 0; c < 4; c++) acc[i][j][c] = 0.0f;

    gemm_mainloop(sb, tid, wm, wn, lid,
                  (const char*)(Ahi + (size_t)m0 * DM),
                  (const char*)(Alo + (size_t)m0 * DM),
                  (const char*)(Bhi + (size_t)n0 * DM),
                  (const char*)(Blo + (size_t)n0 * DM), acc);

    #pragma unroll
    for (int mt = 0; mt < 4; mt++) {
        const int row0 = m0 + (wm << 6) + (mt << 4) + (lid >> 2);
        #pragma unroll
        for (int nt = 0; nt < 4; nt++) {
            const int col = n0 + (wn << 5) + (nt << 3) + ((lid & 3) << 1);
            const float b0 = bias[col], b1 = bias[col + 1];
            uint32_t h, l;
            split2((acc[mt][nt][0] + b0) * sc, (acc[mt][nt][1] + b1) * sc, h, l);
            *(uint32_t*)&Chi[(size_t)row0 * DM + col] = h;
            *(uint32_t*)&Clo[(size_t)row0 * DM + col] = l;
            split2((acc[mt][nt][2] + b0) * sc, (acc[mt][nt][3] + b1) * sc, h, l);
            *(uint32_t*)&Chi[(size_t)(row0 + 8) * DM + col] = h;
            *(uint32_t*)&Clo[(size_t)(row0 + 8) * DM + col] = l;
        }
    }
}

// ---------------------------------------------------------------------------
// out projection GEMM: fp32 + bias + residual epilogue. grid (4, 128).
// ---------------------------------------------------------------------------
__global__ __launch_bounds__(256) void out_gemm(
    const __nv_bfloat16* __restrict__ Ahi, const __nv_bfloat16* __restrict__ Alo,
    const __nv_bfloat16* __restrict__ Bhi, const __nv_bfloat16* __restrict__ Blo,
    const float* __restrict__ bias, const float* __restrict__ resid,
    float* __restrict__ Cf)
{
    extern __shared__ char smg[];
    const uint32_t sb = smem_u32(smg);
    const int tid = threadIdx.x, wid = tid >> 5, lid = tid & 31;
    const int wm = wid >> 2, wn = wid & 3;
    const int m0 = blockIdx.y << 7, n0 = blockIdx.x << 7;

    float acc[4][4][4];
    #pragma unroll
    for (int i = 0; i < 4; i++)
        #pragma unroll
        for (int j = 0; j < 4; j++)
            #pragma unroll
            for (int c = 0; c < 4; c++) acc[i][j][c] = 0.0f;

    gemm_mainloop(sb, tid, wm, wn, lid,
                  (const char*)(Ahi + (size_t)m0 * DM),
                  (const char*)(Alo + (size_t)m0 * DM),
                  (const char*)(Bhi + (size_t)n0 * DM),
                  (const char*)(Blo + (size_t)n0 * DM), acc);

    #pragma unroll
    for (int mt = 0; mt < 4; mt++) {
        const int row0 = m0 + (wm << 6) + (mt << 4) + (lid >> 2);
        #pragma unroll
        for (int nt = 0; nt < 4; nt++) {
            const int col = n0 + (wn << 5) + (nt << 3) + ((lid & 3) << 1);
            const float b0 = bias[col], b1 = bias[col + 1];
            const float2 r0 = *(const float2*)&resid[(size_t)row0 * DM + col];
            const float2 r1 = *(const float2*)&resid[(size_t)(row0 + 8) * DM + col];
            *(float2*)&Cf[(size_t)row0 * DM + col] =
                make_float2(acc[mt][nt][0] + b0 + r0.x, acc[mt][nt][1] + b1 + r0.y);
            *(float2*)&Cf[(size_t)(row0 + 8) * DM + col] =
                make_float2(acc[mt][nt][2] + b0 + r1.x, acc[mt][nt][3] + b1 + r1.y);
        }
    }
}

// ---------------------------------------------------------------------------
// HMMA flash attention, split-bf16 3-term, block-causal mask,
// cp.async 2-stage K/V pipeline. 128 q-rows per CTA, 8 warps.
// grid (T/128, H, B), 256 threads; warp w owns q rows [16w, 16w+16).
// Q comes in pre-scaled by 0.125 (folded into qkv_gemm epilogue).
// smem: Q hi/lo (36864 B) + 2 stages x {Kh,Kl,Vh,Vl} (36864 B each).
// ---------------------------------------------------------------------------
#define ATP      144
#define AQH      0
#define AQL      (128 * ATP)
#define ASTAGE0  (2 * 128 * ATP)           // 36864
#define STG_SZ   (4 * 64 * ATP)            // 36864 per stage
#define SKH      0
#define SKL      (64 * ATP)
#define SVH      (2 * 64 * ATP)
#define SVL      (3 * 64 * ATP)
#define AT_SMEM  (ASTAGE0 + 2 * STG_SZ)    // 110592 B

__global__ __launch_bounds__(256, 2) void attn_hmma(
    const __nv_bfloat16* __restrict__ Qh, const __nv_bfloat16* __restrict__ Ql,
    const __nv_bfloat16* __restrict__ Kh, const __nv_bfloat16* __restrict__ Kl,
    const __nv_bfloat16* __restrict__ Vh, const __nv_bfloat16* __restrict__ Vl,
    __nv_bfloat16* __restrict__ Ch, __nv_bfloat16* __restrict__ Cl)
{
    extern __shared__ char sma[];
    const uint32_t sb = smem_u32(sma);
    const int tid = threadIdx.x, wid = tid >> 5, lid = tid & 31;
    const int b = blockIdx.z, h = blockIdx.y;
    const int t0 = blockIdx.x << 7;

    const int nblocks = ((t0 + 127) >> 8) + 1;
    const char* gkh = (const char*)(Kh + (size_t)b * PP * DM + h * HD);
    const char* gkl = (const char*)(Kl + (size_t)b * PP * DM + h * HD);
    const char* gvh = (const char*)(Vh + (size_t)b * PP * DM + h * HD);
    const char* gvl = (const char*)(Vl + (size_t)b * PP * DM + h * HD);

    // ---- prologue: async-load Q tile (128 rows) + stage 0 K/V ----
    {
        const char* gqh = (const char*)(Qh + (size_t)(b * TT + t0) * DM + h * HD);
        const char* gql = (const char*)(Ql + (size_t)(b * TT + t0) * DM + h * HD);
        #pragma unroll
        for (int i = 0; i < 4; i++) {        // Q: 1024 chunks / 256 thr
            int idx = tid + (i << 8);
            int r = idx >> 3, c16 = (idx & 7) << 4;
            size_t go = (size_t)r * 1024 + c16;
            uint32_t so = r * ATP + c16;
            cp16(sb + AQH + so, gqh + go);
            cp16(sb + AQL + so, gql + go);
        }
        #pragma unroll
        for (int i = 0; i < 2; i++) {        // K/V: 512 chunks x 4 tiles
            int idx = tid + (i << 8);
            int r = idx >> 3, c16 = (idx & 7) << 4;
            size_t go = (size_t)r * 1024 + c16;
            uint32_t so = r * ATP + c16;
            cp16(sb + ASTAGE0 + SKH + so, gkh + go);
            cp16(sb + ASTAGE0 + SKL + so, gkl + go);
            cp16(sb + ASTAGE0 + SVH + so, gvh + go);
            cp16(sb + ASTAGE0 + SVL + so, gvl + go);
        }
        cp_commit();
    }

    float S[8][4], O[8][4];
    #pragma unroll
    for (int nt = 0; nt < 8; nt++)
        #pragma unroll
        for (int e = 0; e < 4; e++) O[nt][e] = 0.0f;
    float mrun0 = -1e30f, mrun1 = -1e30f, lrun0 = 0.0f, lrun1 = 0.0f;

    const uint32_t a_ad0 = sb + AQH + ((wid << 4) + (lid & 15)) * ATP + ((lid >> 4) << 4);
    const uint32_t b_row = ((lid >> 3) & 1) * 8 + (lid & 7);
    const uint32_t b_cb  = (lid >> 4) << 4;

    const int trow = t0 + (wid << 4) + (lid >> 2);
    const int lim0 = trow >> 2;
    const int lim1 = (trow + 8) >> 2;

    for (int kb = 0; kb < nblocks; kb++) {
        const int p0 = kb << 6;
        const uint32_t stg = ASTAGE0 + (uint32_t)(kb & 1) * STG_SZ;

        // prefetch next K/V stage
        if (kb + 1 < nblocks) {
            const uint32_t nstg = ASTAGE0 + (uint32_t)((kb + 1) & 1) * STG_SZ;
            const size_t pb = (size_t)(p0 + 64) * 1024;
            #pragma unroll
            for (int i = 0; i < 2; i++) {
                int idx = tid + (i << 8);
                int r = idx >> 3, c16 = (idx & 7) << 4;
                size_t go = pb + (size_t)r * 1024 + c16;
                uint32_t so = r * ATP + c16;
                cp16(sb + nstg + SKH + so, gkh + go);
                cp16(sb + nstg + SKL + so, gkl + go);
                cp16(sb + nstg + SVH + so, gvh + go);
                cp16(sb + nstg + SVL + so, gvl + go);
            }
            cp_commit();
            cp_wait<1>();
        } else {
            cp_wait<0>();
        }
        __syncthreads();

        // ---- scores S = Q K^T via 3-term HMMA (Q pre-scaled) ----
        #pragma unroll
        for (int nt = 0; nt < 8; nt++)
            #pragma unroll
            for (int e = 0; e < 4; e++) S[nt][e] = 0.0f;

        #pragma unroll
        for (int ks = 0; ks < 4; ks++) {
            const uint32_t kbyte = ks << 5;
            uint32_t ah[4], al[4];
            ldsm_x4(ah[0], ah[1], ah[2], ah[3], a_ad0 + kbyte);
            ldsm_x4(al[0], al[1], al[2], al[3], a_ad0 + (AQL - AQH) + kbyte);
            #pragma unroll
            for (int ntp = 0; ntp < 4; ntp++) {
                uint32_t bd = sb + stg + SKH + ((ntp << 4) + b_row) * ATP + kbyte + b_cb;
                uint32_t r0, r1, r2, r3;
                uint32_t bh0[2], bh1[2], bl0[2], bl1[2];
                ldsm_x4(r0, r1, r2, r3, bd);
                bh0[0] = r0; bh1[0] = r1; bh0[1] = r2; bh1[1] = r3;
                ldsm_x4(r0, r1, r2, r3, bd + (SKL - SKH));
                bl0[0] = r0; bl1[0] = r1; bl0[1] = r2; bl1[1] = r3;
                mma16816(S[2 * ntp],     ah, bh0);
                mma16816(S[2 * ntp],     ah, bl0);
                mma16816(S[2 * ntp],     al, bh0);
                mma16816(S[2 * ntp + 1], ah, bh1);
                mma16816(S[2 * ntp + 1], ah, bl1);
                mma16816(S[2 * ntp + 1], al, bh1);
            }
        }

        if (kb == nblocks - 1) {
            const int cb = p0 + ((lid & 3) << 1);
            #pragma unroll
            for (int nt = 0; nt < 8; nt++) {
                const int c0 = cb + (nt << 3), c1 = c0 + 1;
                if (c0 > lim0) S[nt][0] = -1e30f;
                if (c1 > lim0) S[nt][1] = -1e30f;
                if (c0 > lim1) S[nt][2] = -1e30f;
                if (c1 > lim1) S[nt][3] = -1e30f;
            }
        }

        // ---- online softmax (rows trow, trow+8) ----
        float rm0 = -1e30f, rm1 = -1e30f;
        #pragma unroll
        for (int nt = 0; nt < 8; nt++) {
            rm0 = fmaxf(rm0, fmaxf(S[nt][0], S[nt][1]));
            rm1 = fmaxf(rm1, fmaxf(S[nt][2], S[nt][3]));
        }
        rm0 = fmaxf(rm0, __shfl_xor_sync(0xffffffffu, rm0, 1));
        rm0 = fmaxf(rm0, __shfl_xor_sync(0xffffffffu, rm0, 2));
        rm1 = fmaxf(rm1, __shfl_xor_sync(0xffffffffu, rm1, 1));
        rm1 = fmaxf(rm1, __shfl_xor_sync(0xffffffffu, rm1, 2));

        const float mn0 = fmaxf(mrun0, rm0), mn1 = fmaxf(mrun1, rm1);
        const float al0 = __expf(mrun0 - mn0), al1 = __expf(mrun1 - mn1);
        float s0 = 0.0f, s1 = 0.0f;
        #pragma unroll
        for (int nt = 0; nt < 8; nt++) {
            float p0e = __expf(S[nt][0] - mn0);
            float p1e = __expf(S[nt][1] - mn0);
            float p2e = __expf(S[nt][2] - mn1);
            float p3e = __expf(S[nt][3] - mn1);
            S[nt][0] = p0e; S[nt][1] = p1e; S[nt][2] = p2e; S[nt][3] = p3e;
            s0 += p0e + p1e; s1 += p2e + p3e;
            O[nt][0] *= al0; O[nt][1] *= al0;
            O[nt][2] *= al1; O[nt][3] *= al1;
        }
        s0 += __shfl_xor_sync(0xffffffffu, s0, 1);
        s0 += __shfl_xor_sync(0xffffffffu, s0, 2);
        s1 += __shfl_xor_sync(0xffffffffu, s1, 1);
        s1 += __shfl_xor_sync(0xffffffffu, s1, 2);
        lrun0 = lrun0 * al0 + s0; lrun1 = lrun1 * al1 + s1;
        mrun0 = mn0; mrun1 = mn1;

        // ---- O += P V ----
        #pragma unroll
        for (int ks = 0; ks < 4; ks++) {
            const int nt0 = 2 * ks, nt1 = 2 * ks + 1;
            uint32_t aph[4], apl[4];
            split2(S[nt0][0], S[nt0][1], aph[0], apl[0]);
            split2(S[nt0][2], S[nt0][3], aph[1], apl[1]);
            split2(S[nt1][0], S[nt1][1], aph[2], apl[2]);
            split2(S[nt1][2], S[nt1][3], aph[3], apl[3]);

            #pragma unroll
            for (int nv = 0; nv < 4; nv++) {
                uint32_t vd = sb + stg + SVH + ((ks << 4) + b_row) * ATP + (nv << 5) + b_cb;
                uint32_t r0, r1, r2, r3;
                uint32_t vh0[2], vh1[2], vl0[2], vl1[2];
                ldsm_x4_t(r0, r1, r2, r3, vd);
                vh0[0] = r0; vh0[1] = r1; vh1[0] = r2; vh1[1] = r3;
                ldsm_x4_t(r0, r1, r2, r3, vd + (SVL - SVH));
                vl0[0] = r0; vl0[1] = r1; vl1[0] = r2; vl1[1] = r3;
                mma16816(O[2 * nv],     aph, vh0);
                mma16816(O[2 * nv],     aph, vl0);
                mma16816(O[2 * nv],     apl, vh0);
                mma16816(O[2 * nv + 1], aph, vh1);
                mma16816(O[2 * nv + 1], aph, vl1);
                mma16816(O[2 * nv + 1], apl, vh1);
            }
        }
        __syncthreads();   // all reads of stage done before its refill (kb+2)
    }

    // ---- normalize + write ctx hi/lo ----
    const float inv0 = 1.0f / lrun0, inv1 = 1.0f / lrun1;
    const size_t row0 = (size_t)(b * TT) + trow;
    #pragma unroll
    for (int nt = 0; nt < 8; nt++) {
        const int col = h * HD + (nt << 3) + ((lid & 3) << 1);
        uint32_t hh, ll;
        split2(O[nt][0] * inv0, O[nt][1] * inv0, hh, ll);
        *(uint32_t*)&Ch[row0 * DM + col] = hh;
        *(uint32_t*)&Cl[row0 * DM + col] = ll;
        split2(O[nt][2] * inv1, O[nt][3] * inv1, hh, ll);
        *(uint32_t*)&Ch[(row0 + 8) * DM + col] = hh;
        *(uint32_t*)&Cl[(row0 + 8) * DM + col] = ll;
    }
}

// ---------------------------------------------------------------------------
extern "C" void kernel_launch(void* const* d_in, const int* in_sizes, int n_in,
                              void* d_out, int out_size)
{
    (void)in_sizes; (void)n_in; (void)out_size;
    const float* tok   = (const float*)d_in[0];
    const float* patch = (const float*)d_in[1];
    const float* Wq    = (const float*)d_in[2];
    const float* Wk    = (const float*)d_in[3];
    const float* Wv    = (const float*)d_in[4];
    const float* bq    = (const float*)d_in[5];
    const float* bk    = (const float*)d_in[6];
    const float* bv    = (const float*)d_in[7];
    const float* Wo    = (const float*)d_in[8];
    const float* bo    = (const float*)d_in[9];
    float* out = (float*)d_out;

    __nv_bfloat16 *qh, *ql, *kh, *kl, *vh, *vl;
    __nv_bfloat16 *tkh, *tkl, *pth, *ptl, *cxh, *cxl, *wth, *wtl;
    cudaGetSymbolAddress((void**)&qh,  g_Qh);
    cudaGetSymbolAddress((void**)&ql,  g_Ql);
    cudaGetSymbolAddress((void**)&kh,  g_Kh);
    cudaGetSymbolAddress((void**)&kl,  g_Kl);
    cudaGetSymbolAddress((void**)&vh,  g_Vh);
    cudaGetSymbolAddress((void**)&vl,  g_Vl);
    cudaGetSymbolAddress((void**)&tkh, g_tok_hi);
    cudaGetSymbolAddress((void**)&tkl, g_tok_lo);
    cudaGetSymbolAddress((void**)&pth, g_pat_hi);
    cudaGetSymbolAddress((void**)&ptl, g_pat_lo);
    cudaGetSymbolAddress((void**)&cxh, g_ctx_hi);
    cudaGetSymbolAddress((void**)&cxl, g_ctx_lo);
    cudaGetSymbolAddress((void**)&wth, g_Wt_hi);
    cudaGetSymbolAddress((void**)&wtl, g_Wt_lo);

    static bool attr_set = false;
    if (!attr_set) {
        cudaFuncSetAttribute(qkv_gemm,
                             cudaFuncAttributeMaxDynamicSharedMemorySize, GSMEM);
        cudaFuncSetAttribute(out_gemm,
                             cudaFuncAttributeMaxDynamicSharedMemorySize, GSMEM);
        cudaFuncSetAttribute(attn_hmma,
                             cudaFuncAttributeMaxDynamicSharedMemorySize, AT_SMEM);
        attr_set = true;
    }

    const int nTok4 = BB * TT * DM / 4;
    const int nPat4 = BB * PP * DM / 4;

    // split inputs into bf16 hi/lo
    conv_hilo<<<nTok4 / 256, 256>>>((const float4*)tok,
        (__nv_bfloat162*)tkh, (__nv_bfloat162*)tkl, nTok4);
    conv_hilo<<<nPat4 / 256, 256>>>((const float4*)patch,
        (__nv_bfloat162*)pth, (__nv_bfloat162*)ptl, nPat4);
    conv_wt4<<<dim3(16, 16, 4), dim3(32, 8)>>>(Wq, Wk, Wv, Wo, wth, wtl);

    // fused Q/K/V projections -> bf16 hi/lo (Q pre-scaled by 0.125)
    qkv_gemm<<<dim3(4, 192), 256, GSMEM>>>(
        tkh, tkl, pth, ptl, wth, wtl, bq, bk, bv,
        qh, ql, kh, kl, vh, vl);

    // HMMA flash attention -> ctx hi/lo
    attn_hmma<<<dim3(TT / 128, NH, BB), 256, AT_SMEM>>>(
        qh, ql, kh, kl, vh, vl, cxh, cxl);

    // out projection + bias + residual -> fp32 output
    out_gemm<<<dim3(4, 128), 256, GSMEM>>>(
        cxh, cxl, wth + 3 * (size_t)DM * DM, wtl + 3 * (size_t)DM * DM,
        bo, tok, out);
}